// round 7
// baseline (speedup 1.0000x reference)
#include <cuda_runtime.h>
#include <cuda_bf16.h>
#include <cstdint>

#define TRAJ      25
#define NT        10
#define NS        10
#define GDIM      200
#define MAP_ELEMS 8000000
#define VFOV_C    0.3490658503988659f
#define MAX_BT    (1024 * TRAJ * NT)   // supports outer up to 1024

// Staging: packed (pos_voxel.xyz, pen) and (gdir_voxel.xyz, unused) per (b,t).
__device__ float4 g_pos4[MAX_BT];
__device__ float4 g_gd4[MAX_BT];

// ---------- kernel 1: per-(b,t) prelude ----------
__global__ __launch_bounds__(256) void prelude_kernel(
    const float* __restrict__ Df, const float* __restrict__ Dp,
    const float* __restrict__ goal, const float* __restrict__ L,
    const float* __restrict__ minb, const int* __restrict__ map_id,
    float* __restrict__ out, int n_bt)
{
    const int n = blockIdx.x * blockDim.x + threadIdx.x;
    if (n >= n_bt) return;
    const int b  = n / NT;
    const int it = n - b * NT;
    const int o  = b / TRAJ;

    const float t = 0.66f + (float)it * ((1.32f - 0.66f) / 9.0f);

    float pos[3], vel[3];
    #pragma unroll
    for (int c = 0; c < 3; c++) {
        const float d0 = __ldg(Df + b * 9 + c * 3 + 0);
        const float d1 = __ldg(Df + b * 9 + c * 3 + 1);
        const float d2 = __ldg(Df + b * 9 + c * 3 + 2);
        const float d3 = __ldg(Dp + b * 9 + c * 3 + 0);
        const float d4 = __ldg(Dp + b * 9 + c * 3 + 1);
        const float d5 = __ldg(Dp + b * 9 + c * 3 + 2);
        float coe[6];
        #pragma unroll
        for (int i = 0; i < 6; i++) {
            coe[i] = __ldg(L + i * 6 + 0) * d0 + __ldg(L + i * 6 + 1) * d1
                   + __ldg(L + i * 6 + 2) * d2 + __ldg(L + i * 6 + 3) * d3
                   + __ldg(L + i * 6 + 4) * d4 + __ldg(L + i * 6 + 5) * d5;
        }
        float p = coe[5];
        p = p * t + coe[4];
        p = p * t + coe[3];
        p = p * t + coe[2];
        p = p * t + coe[1];
        p = p * t + coe[0];
        pos[c] = p;
        float v = 5.0f * coe[5];
        v = v * t + 4.0f * coe[4];
        v = v * t + 3.0f * coe[3];
        v = v * t + 2.0f * coe[2];
        v = v * t + coe[1];
        vel[c] = v;
    }

    const float gx0 = __ldg(goal + (long long)o * TRAJ * 3 + 0);
    const float gy0 = __ldg(goal + (long long)o * TRAJ * 3 + 1);
    const float gz0 = __ldg(goal + (long long)o * TRAJ * 3 + 2);
    const float gdx = gx0 - pos[0];
    const float gdy = gy0 - pos[1];
    const float gdz = gz0 - pos[2];

    const float pg = atan2f(gdz, sqrtf(gdx * gdx + gdy * gdy + 1e-6f));
    const float pv = atan2f(vel[2], sqrtf(vel[0] * vel[0] + vel[1] * vel[1] + 1e-6f));
    const float pen = fmaxf(fabsf(pg - pv) - VFOV_C, 0.0f);

    const int   m   = __ldg(map_id + o);
    const float mb0 = __ldg(minb + m * 3 + 0);
    const float mb1 = __ldg(minb + m * 3 + 1);
    const float mb2 = __ldg(minb + m * 3 + 2);

    g_pos4[n] = make_float4((pos[0] - mb0) * 5.0f,
                            (pos[1] - mb1) * 5.0f,
                            (pos[2] - mb2) * 5.0f, pen);
    g_gd4[n]  = make_float4(gdx * 5.0f, gdy * 5.0f, gdz * 5.0f, 0.0f);

    if (it == 0) out[b] = 0.0f;   // zero-init before gather kernel's atomics
}

// ---------- kernel 2: TWO trilinear samples per thread via cp.async ----------
// grid (outer, NS/2); tid<250 -> (traj j, time it); samples s0, s0+5.
// cp.async decouples gather MLP from registers: 16 outstanding 4B copies per
// thread with ONE wait, instead of register-throttled 2-4 deep LDG chains.
__global__ __launch_bounds__(256) void gather_kernel(
    const float* __restrict__ sdf, const int* __restrict__ map_id,
    float* __restrict__ out)
{
    const int o   = blockIdx.x;
    const int s0  = blockIdx.y;          // samples s0 and s0+5
    const int tid = threadIdx.x;

    __shared__ float sBuf[256][17];      // 16 corners + 1 pad (bank spread)
    __shared__ float sC[TRAJ * NT];

    float w = 0.0f;
    if (tid < TRAJ * NT) {
        const int n = (o * TRAJ) * NT + tid;

        const float4 p4 = __ldg(g_pos4 + n);
        const float4 g4 = __ldg(g_gd4 + n);

        const float* __restrict__ map =
            sdf + (long long)__ldg(map_id + o) * MAP_ELEMS;

        // --- coordinates / bases for both samples ---
        float fx[2], fy[2], fz[2];
        bool  valid[2];
        int   base[2];
        #pragma unroll
        for (int k = 0; k < 2; k++) {
            const float a  = (float)(s0 + 5 * k) * (1.0f / 9.0f);
            const float vx = p4.x + a * g4.x;
            const float vy = p4.y + a * g4.y;
            const float vz = p4.z + a * g4.z;
            valid[k] = (vx > 0.5f) && (vx < (float)GDIM - 1.5f)
                    && (vy > 0.5f) && (vy < (float)GDIM - 1.5f)
                    && (vz > 0.5f) && (vz < (float)GDIM - 1.5f);
            const float x0f = fminf(fmaxf(floorf(vx), 0.0f), (float)(GDIM - 2));
            const float y0f = fminf(fmaxf(floorf(vy), 0.0f), (float)(GDIM - 2));
            const float z0f = fminf(fmaxf(floorf(vz), 0.0f), (float)(GDIM - 2));
            fx[k] = vx - x0f; fy[k] = vy - y0f; fz[k] = vz - z0f;
            int bb = (int)z0f * (GDIM * GDIM) + (int)y0f * GDIM + (int)x0f;
            base[k] = valid[k] ? bb : 0;   // safe dummy address
        }

        // --- issue all 16 gathers as cp.async (no dest registers) ---
        const uint32_t sdst =
            (uint32_t)__cvta_generic_to_shared(&sBuf[tid][0]);
        #pragma unroll
        for (int k = 0; k < 2; k++) {
            const float* gp = map + base[k];
            const uint32_t d = sdst + k * 32;
            asm volatile("cp.async.ca.shared.global [%0], [%1], 4;\n"
                         :: "r"(d +  0), "l"(gp) : "memory");
            asm volatile("cp.async.ca.shared.global [%0], [%1], 4;\n"
                         :: "r"(d +  4), "l"(gp + 1) : "memory");
            asm volatile("cp.async.ca.shared.global [%0], [%1], 4;\n"
                         :: "r"(d +  8), "l"(gp + GDIM) : "memory");
            asm volatile("cp.async.ca.shared.global [%0], [%1], 4;\n"
                         :: "r"(d + 12), "l"(gp + GDIM + 1) : "memory");
            asm volatile("cp.async.ca.shared.global [%0], [%1], 4;\n"
                         :: "r"(d + 16), "l"(gp + GDIM * GDIM) : "memory");
            asm volatile("cp.async.ca.shared.global [%0], [%1], 4;\n"
                         :: "r"(d + 20), "l"(gp + GDIM * GDIM + 1) : "memory");
            asm volatile("cp.async.ca.shared.global [%0], [%1], 4;\n"
                         :: "r"(d + 24), "l"(gp + GDIM * GDIM + GDIM) : "memory");
            asm volatile("cp.async.ca.shared.global [%0], [%1], 4;\n"
                         :: "r"(d + 28), "l"(gp + GDIM * GDIM + GDIM + 1) : "memory");
        }
        asm volatile("cp.async.wait_all;\n" ::: "memory");

        // --- consume from shared ---
        #pragma unroll
        for (int k = 0; k < 2; k++) {
            const float* c = &sBuf[tid][k * 8];
            const float omx = 1.0f - fx[k], omy = 1.0f - fy[k];
            const float l0 = (c[0] * omx + c[1] * fx[k]) * omy
                           + (c[2] * omx + c[3] * fx[k]) * fy[k];
            const float l1 = (c[4] * omx + c[5] * fx[k]) * omy
                           + (c[6] * omx + c[7] * fx[k]) * fy[k];
            const float dist = l0 * (1.0f - fz[k]) + l1 * fz[k];
            const float cost = valid[k] ? __expf(-(dist - 0.6f) * (1.0f / 0.3f))
                                        : 0.0f;
            w += 0.2f * fmaxf(0.2f - cost, 0.0f);
        }

        if (s0 == 0) w += 0.5f * p4.w;   // fold pitch term once
        sC[tid] = w;
    }
    __syncthreads();

    if (tid < TRAJ) {
        float v = 0.0f;
        #pragma unroll
        for (int k = 0; k < NT; k++) v += sC[tid * NT + k];
        atomicAdd(&out[o * TRAJ + tid], v);
    }
}

extern "C" void kernel_launch(void* const* d_in, const int* in_sizes, int n_in,
                              void* d_out, int out_size)
{
    const float* Df     = (const float*)d_in[0];
    const float* Dp     = (const float*)d_in[1];
    const float* goal   = (const float*)d_in[2];
    const float* L      = (const float*)d_in[3];
    const float* sdf    = (const float*)d_in[4];
    const float* minb   = (const float*)d_in[5];
    const int*   map_id = (const int*)d_in[6];
    float* out = (float*)d_out;

    const int outer = in_sizes[6];
    const int n_bt  = outer * TRAJ * NT;

    prelude_kernel<<<(n_bt + 255) / 256, 256>>>(Df, Dp, goal, L, minb, map_id,
                                                out, n_bt);
    dim3 grid(outer, NS / 2);
    gather_kernel<<<grid, 256>>>(sdf, map_id, out);
}

// round 8
// speedup vs baseline: 1.1079x; 1.1079x over previous
#include <cuda_runtime.h>
#include <cuda_bf16.h>
#include <cstdint>

#define TRAJ      25
#define NT        10
#define NS        10
#define GDIM      200
#define MAP_ELEMS 8000000
#define VFOV_C    0.3490658503988659f
#define MAX_BT    (1024 * TRAJ * NT)   // supports outer up to 1024

// Staging: packed (pos_voxel.xyz, pen) and (gdir_voxel.xyz, 0) per (b,t).
__device__ float4 g_pos4[MAX_BT];
__device__ float4 g_gd4[MAX_BT];

// ---------- kernel 1: per-(b,t) prelude ----------
__global__ __launch_bounds__(256) void prelude_kernel(
    const float* __restrict__ Df, const float* __restrict__ Dp,
    const float* __restrict__ goal, const float* __restrict__ L,
    const float* __restrict__ minb, const int* __restrict__ map_id,
    float* __restrict__ out, int n_bt)
{
    const int n = blockIdx.x * blockDim.x + threadIdx.x;
    if (n >= n_bt) return;
    const int b  = n / NT;
    const int it = n - b * NT;
    const int o  = b / TRAJ;

    const float t = 0.66f + (float)it * ((1.32f - 0.66f) / 9.0f);

    float pos[3], vel[3];
    #pragma unroll
    for (int c = 0; c < 3; c++) {
        const float d0 = __ldg(Df + b * 9 + c * 3 + 0);
        const float d1 = __ldg(Df + b * 9 + c * 3 + 1);
        const float d2 = __ldg(Df + b * 9 + c * 3 + 2);
        const float d3 = __ldg(Dp + b * 9 + c * 3 + 0);
        const float d4 = __ldg(Dp + b * 9 + c * 3 + 1);
        const float d5 = __ldg(Dp + b * 9 + c * 3 + 2);
        float coe[6];
        #pragma unroll
        for (int i = 0; i < 6; i++) {
            coe[i] = __ldg(L + i * 6 + 0) * d0 + __ldg(L + i * 6 + 1) * d1
                   + __ldg(L + i * 6 + 2) * d2 + __ldg(L + i * 6 + 3) * d3
                   + __ldg(L + i * 6 + 4) * d4 + __ldg(L + i * 6 + 5) * d5;
        }
        float p = coe[5];
        p = p * t + coe[4];
        p = p * t + coe[3];
        p = p * t + coe[2];
        p = p * t + coe[1];
        p = p * t + coe[0];
        pos[c] = p;
        float v = 5.0f * coe[5];
        v = v * t + 4.0f * coe[4];
        v = v * t + 3.0f * coe[3];
        v = v * t + 2.0f * coe[2];
        v = v * t + coe[1];
        vel[c] = v;
    }

    const float gx0 = __ldg(goal + (long long)o * TRAJ * 3 + 0);
    const float gy0 = __ldg(goal + (long long)o * TRAJ * 3 + 1);
    const float gz0 = __ldg(goal + (long long)o * TRAJ * 3 + 2);
    const float gdx = gx0 - pos[0];
    const float gdy = gy0 - pos[1];
    const float gdz = gz0 - pos[2];

    const float pg = atan2f(gdz, sqrtf(gdx * gdx + gdy * gdy + 1e-6f));
    const float pv = atan2f(vel[2], sqrtf(vel[0] * vel[0] + vel[1] * vel[1] + 1e-6f));
    const float pen = fmaxf(fabsf(pg - pv) - VFOV_C, 0.0f);

    const int   m   = __ldg(map_id + o);
    const float mb0 = __ldg(minb + m * 3 + 0);
    const float mb1 = __ldg(minb + m * 3 + 1);
    const float mb2 = __ldg(minb + m * 3 + 2);

    g_pos4[n] = make_float4((pos[0] - mb0) * 5.0f,
                            (pos[1] - mb1) * 5.0f,
                            (pos[2] - mb2) * 5.0f, pen);
    g_gd4[n]  = make_float4(gdx * 5.0f, gdy * 5.0f, gdz * 5.0f, 0.0f);

    if (it == 0) out[b] = 0.0f;   // zero-init before gather kernel's atomics
}

// 8 ordered non-caching corner loads via inline PTX (ptxas cannot sink these
// past later consumption; keeps all batches in flight simultaneously).
#define LOAD8(gp, c0, c1, c2, c3, c4, c5, c6, c7)                              \
    asm volatile(                                                              \
        "ld.global.nc.f32 %0, [%8];\n\t"                                       \
        "ld.global.nc.f32 %1, [%8+4];\n\t"                                     \
        "ld.global.nc.f32 %2, [%8+800];\n\t"                                   \
        "ld.global.nc.f32 %3, [%8+804];\n\t"                                   \
        "ld.global.nc.f32 %4, [%8+160000];\n\t"                                \
        "ld.global.nc.f32 %5, [%8+160004];\n\t"                                \
        "ld.global.nc.f32 %6, [%8+160800];\n\t"                                \
        "ld.global.nc.f32 %7, [%8+160804];\n\t"                                \
        : "=f"(c0), "=f"(c1), "=f"(c2), "=f"(c3),                              \
          "=f"(c4), "=f"(c5), "=f"(c6), "=f"(c7)                               \
        : "l"(gp))

// ---------- kernel 2: FIVE trilinear samples per thread ----------
// grid (outer, 2); tid<250 -> (traj j, time it); samples s = s0*5 + 0..4.
// All 40 corner loads issued before any consumption -> ~40 outstanding
// loads per thread, 640 per SM at 16 warps: covers ~400cyc gather latency.
__global__ __launch_bounds__(256, 2) void gather_kernel(
    const float* __restrict__ sdf, const int* __restrict__ map_id,
    float* __restrict__ out)
{
    const int o   = blockIdx.x;
    const int s0  = blockIdx.y;          // s-half: samples s0*5 .. s0*5+4
    const int tid = threadIdx.x;

    __shared__ float sC[TRAJ * NT];

    float w = 0.0f;
    if (tid < TRAJ * NT) {
        const int n = (o * TRAJ) * NT + tid;

        const float4 p4 = __ldg(g_pos4 + n);
        const float4 g4 = __ldg(g_gd4 + n);

        const float* __restrict__ map =
            sdf + (long long)__ldg(map_id + o) * MAP_ELEMS;

        // --- coordinates / bases for all 5 samples ---
        float fx[5], fy[5], fz[5];
        bool  valid[5];
        const float* gp[5];
        #pragma unroll
        for (int k = 0; k < 5; k++) {
            const float a  = (float)(s0 * 5 + k) * (1.0f / 9.0f);
            const float vx = p4.x + a * g4.x;
            const float vy = p4.y + a * g4.y;
            const float vz = p4.z + a * g4.z;
            valid[k] = (vx > 0.5f) && (vx < (float)GDIM - 1.5f)
                    && (vy > 0.5f) && (vy < (float)GDIM - 1.5f)
                    && (vz > 0.5f) && (vz < (float)GDIM - 1.5f);
            const float x0f = fminf(fmaxf(floorf(vx), 0.0f), (float)(GDIM - 2));
            const float y0f = fminf(fmaxf(floorf(vy), 0.0f), (float)(GDIM - 2));
            const float z0f = fminf(fmaxf(floorf(vz), 0.0f), (float)(GDIM - 2));
            fx[k] = vx - x0f; fy[k] = vy - y0f; fz[k] = vz - z0f;
            int bb = (int)z0f * (GDIM * GDIM) + (int)y0f * GDIM + (int)x0f;
            gp[k] = map + (valid[k] ? bb : 0);
        }

        // --- issue ALL 40 gathers back-to-back ---
        float c[5][8];
        LOAD8(gp[0], c[0][0], c[0][1], c[0][2], c[0][3],
                     c[0][4], c[0][5], c[0][6], c[0][7]);
        LOAD8(gp[1], c[1][0], c[1][1], c[1][2], c[1][3],
                     c[1][4], c[1][5], c[1][6], c[1][7]);
        LOAD8(gp[2], c[2][0], c[2][1], c[2][2], c[2][3],
                     c[2][4], c[2][5], c[2][6], c[2][7]);
        LOAD8(gp[3], c[3][0], c[3][1], c[3][2], c[3][3],
                     c[3][4], c[3][5], c[3][6], c[3][7]);
        LOAD8(gp[4], c[4][0], c[4][1], c[4][2], c[4][3],
                     c[4][4], c[4][5], c[4][6], c[4][7]);

        // --- consume ---
        #pragma unroll
        for (int k = 0; k < 5; k++) {
            const float omx = 1.0f - fx[k], omy = 1.0f - fy[k];
            const float l0 = (c[k][0] * omx + c[k][1] * fx[k]) * omy
                           + (c[k][2] * omx + c[k][3] * fx[k]) * fy[k];
            const float l1 = (c[k][4] * omx + c[k][5] * fx[k]) * omy
                           + (c[k][6] * omx + c[k][7] * fx[k]) * fy[k];
            const float dist = l0 * (1.0f - fz[k]) + l1 * fz[k];
            const float cost = valid[k] ? __expf(-(dist - 0.6f) * (1.0f / 0.3f))
                                        : 0.0f;
            w += 0.2f * fmaxf(0.2f - cost, 0.0f);
        }

        if (s0 == 0) w += 0.5f * p4.w;   // fold pitch term once
        sC[tid] = w;
    }
    __syncthreads();

    if (tid < TRAJ) {
        float v = 0.0f;
        #pragma unroll
        for (int k = 0; k < NT; k++) v += sC[tid * NT + k];
        atomicAdd(&out[o * TRAJ + tid], v);
    }
}

extern "C" void kernel_launch(void* const* d_in, const int* in_sizes, int n_in,
                              void* d_out, int out_size)
{
    const float* Df     = (const float*)d_in[0];
    const float* Dp     = (const float*)d_in[1];
    const float* goal   = (const float*)d_in[2];
    const float* L      = (const float*)d_in[3];
    const float* sdf    = (const float*)d_in[4];
    const float* minb   = (const float*)d_in[5];
    const int*   map_id = (const int*)d_in[6];
    float* out = (float*)d_out;

    const int outer = in_sizes[6];
    const int n_bt  = outer * TRAJ * NT;

    prelude_kernel<<<(n_bt + 255) / 256, 256>>>(Df, Dp, goal, L, minb, map_id,
                                                out, n_bt);
    dim3 grid(outer, 2);
    gather_kernel<<<grid, 256>>>(sdf, map_id, out);
}

// round 9
// speedup vs baseline: 1.2467x; 1.1252x over previous
#include <cuda_runtime.h>
#include <cuda_bf16.h>
#include <cstdint>

#define TRAJ      25
#define NT        10
#define NS        10
#define GDIM      200
#define GD2       (GDIM * GDIM)
#define MAP_ELEMS 8000000
#define VFOV_C    0.3490658503988659f
#define MAX_BT    (1024 * TRAJ * NT)   // supports outer up to 1024

// Staging: packed (pos_voxel.xyz, pen) and (gdir_voxel.xyz, 0) per (b,t).
__device__ float4 g_pos4[MAX_BT];
__device__ float4 g_gd4[MAX_BT];

// ---------- kernel 1: per-(b,t) prelude ----------
__global__ __launch_bounds__(256) void prelude_kernel(
    const float* __restrict__ Df, const float* __restrict__ Dp,
    const float* __restrict__ goal, const float* __restrict__ L,
    const float* __restrict__ minb, const int* __restrict__ map_id,
    float* __restrict__ out, int n_bt)
{
    const int n = blockIdx.x * blockDim.x + threadIdx.x;
    if (n >= n_bt) return;
    const int b  = n / NT;
    const int it = n - b * NT;
    const int o  = b / TRAJ;

    const float t = 0.66f + (float)it * ((1.32f - 0.66f) / 9.0f);

    float pos[3], vel[3];
    #pragma unroll
    for (int c = 0; c < 3; c++) {
        const float d0 = __ldg(Df + b * 9 + c * 3 + 0);
        const float d1 = __ldg(Df + b * 9 + c * 3 + 1);
        const float d2 = __ldg(Df + b * 9 + c * 3 + 2);
        const float d3 = __ldg(Dp + b * 9 + c * 3 + 0);
        const float d4 = __ldg(Dp + b * 9 + c * 3 + 1);
        const float d5 = __ldg(Dp + b * 9 + c * 3 + 2);
        float coe[6];
        #pragma unroll
        for (int i = 0; i < 6; i++) {
            coe[i] = __ldg(L + i * 6 + 0) * d0 + __ldg(L + i * 6 + 1) * d1
                   + __ldg(L + i * 6 + 2) * d2 + __ldg(L + i * 6 + 3) * d3
                   + __ldg(L + i * 6 + 4) * d4 + __ldg(L + i * 6 + 5) * d5;
        }
        float p = coe[5];
        p = p * t + coe[4];
        p = p * t + coe[3];
        p = p * t + coe[2];
        p = p * t + coe[1];
        p = p * t + coe[0];
        pos[c] = p;
        float v = 5.0f * coe[5];
        v = v * t + 4.0f * coe[4];
        v = v * t + 3.0f * coe[3];
        v = v * t + 2.0f * coe[2];
        v = v * t + coe[1];
        vel[c] = v;
    }

    const float gx0 = __ldg(goal + (long long)o * TRAJ * 3 + 0);
    const float gy0 = __ldg(goal + (long long)o * TRAJ * 3 + 1);
    const float gz0 = __ldg(goal + (long long)o * TRAJ * 3 + 2);
    const float gdx = gx0 - pos[0];
    const float gdy = gy0 - pos[1];
    const float gdz = gz0 - pos[2];

    const float pg = atan2f(gdz, sqrtf(gdx * gdx + gdy * gdy + 1e-6f));
    const float pv = atan2f(vel[2], sqrtf(vel[0] * vel[0] + vel[1] * vel[1] + 1e-6f));
    const float pen = fmaxf(fabsf(pg - pv) - VFOV_C, 0.0f);

    const int   m   = __ldg(map_id + o);
    const float mb0 = __ldg(minb + m * 3 + 0);
    const float mb1 = __ldg(minb + m * 3 + 1);
    const float mb2 = __ldg(minb + m * 3 + 2);

    g_pos4[n] = make_float4((pos[0] - mb0) * 5.0f,
                            (pos[1] - mb1) * 5.0f,
                            (pos[2] - mb2) * 5.0f, pen);
    g_gd4[n]  = make_float4(gdx * 5.0f, gdy * 5.0f, gdz * 5.0f, 0.0f);

    if (it == 0) out[b] = 0.0f;   // zero-init before gather kernel's atomics
}

// ---------- kernel 2: TWO trilinear samples/thread, VECTORIZED corners ----
// grid (outer, NS/2); tid<250 -> (traj j, time it); samples s0, s0+5.
// Each (y,z) row's x-pair is fetched with ONE aligned float4 (+ predicated
// scalar patch for phase 3): 8 scalar LDGs -> 4 vector + ~1 predicated,
// ~halving L1tex per-line replay cost (the measured binding limit).
__global__ __launch_bounds__(256, 2) void gather_kernel(
    const float* __restrict__ sdf, const int* __restrict__ map_id,
    float* __restrict__ out)
{
    const int o   = blockIdx.x;
    const int s0  = blockIdx.y;          // samples s0 and s0+5
    const int tid = threadIdx.x;

    __shared__ float sC[TRAJ * NT];

    float w = 0.0f;
    if (tid < TRAJ * NT) {
        const int n = (o * TRAJ) * NT + tid;

        const float4 p4 = __ldg(g_pos4 + n);
        const float4 g4 = __ldg(g_gd4 + n);

        const float* __restrict__ map =
            sdf + (long long)__ldg(map_id + o) * MAP_ELEMS;

        // --- coordinates / aligned bases for both samples ---
        float fx[2], fy[2], fz[2];
        bool  valid[2];
        int   ab[2];       // 16B-aligned base index (x rounded down to mult 4)
        int   ph[2];       // x alignment phase 0..3
        #pragma unroll
        for (int k = 0; k < 2; k++) {
            const float a  = (float)(s0 + 5 * k) * (1.0f / 9.0f);
            const float vx = p4.x + a * g4.x;
            const float vy = p4.y + a * g4.y;
            const float vz = p4.z + a * g4.z;
            valid[k] = (vx > 0.5f) && (vx < (float)GDIM - 1.5f)
                    && (vy > 0.5f) && (vy < (float)GDIM - 1.5f)
                    && (vz > 0.5f) && (vz < (float)GDIM - 1.5f);
            const float x0f = fminf(fmaxf(floorf(vx), 0.0f), (float)(GDIM - 2));
            const float y0f = fminf(fmaxf(floorf(vy), 0.0f), (float)(GDIM - 2));
            const float z0f = fminf(fmaxf(floorf(vz), 0.0f), (float)(GDIM - 2));
            fx[k] = vx - x0f; fy[k] = vy - y0f; fz[k] = vz - z0f;
            const int x0 = valid[k] ? (int)x0f : 0;
            const int y0 = valid[k] ? (int)y0f : 0;
            const int z0 = valid[k] ? (int)z0f : 0;
            ph[k] = x0 & 3;
            ab[k] = z0 * GD2 + y0 * GDIM + (x0 & ~3);
        }

        // --- issue all vector gathers (rows: y0z0, y1z0, y0z1, y1z1) ---
        // row strides 200 and 40000 are both multiples of 4 -> same phase.
        float4 q[2][4];
        float  ex[2][4];
        #pragma unroll
        for (int k = 0; k < 2; k++) {
            const int roff[4] = {0, GDIM, GD2, GD2 + GDIM};
            #pragma unroll
            for (int r = 0; r < 4; r++)
                q[k][r] = __ldg((const float4*)(map + ab[k] + roff[r]));
            const bool need = (ph[k] == 3);
            #pragma unroll
            for (int r = 0; r < 4; r++)
                ex[k][r] = need ? __ldg(map + ab[k] + roff[r] + 4) : 0.0f;
        }

        // --- consume ---
        #pragma unroll
        for (int k = 0; k < 2; k++) {
            const int p = ph[k];
            float lo[4], hi[4];
            #pragma unroll
            for (int r = 0; r < 4; r++) {
                const float4 v = q[k][r];
                lo[r] = (p == 0) ? v.x : (p == 1) ? v.y : (p == 2) ? v.z : v.w;
                hi[r] = (p == 0) ? v.y : (p == 1) ? v.z : (p == 2) ? v.w
                                                                   : ex[k][r];
            }
            const float omx = 1.0f - fx[k], omy = 1.0f - fy[k];
            const float l0 = (lo[0] * omx + hi[0] * fx[k]) * omy
                           + (lo[1] * omx + hi[1] * fx[k]) * fy[k];
            const float l1 = (lo[2] * omx + hi[2] * fx[k]) * omy
                           + (lo[3] * omx + hi[3] * fx[k]) * fy[k];
            const float dist = l0 * (1.0f - fz[k]) + l1 * fz[k];
            const float cost = valid[k] ? __expf(-(dist - 0.6f) * (1.0f / 0.3f))
                                        : 0.0f;
            w += 0.2f * fmaxf(0.2f - cost, 0.0f);
        }

        if (s0 == 0) w += 0.5f * p4.w;   // fold pitch term once
        sC[tid] = w;
    }
    __syncthreads();

    if (tid < TRAJ) {
        float v = 0.0f;
        #pragma unroll
        for (int k = 0; k < NT; k++) v += sC[tid * NT + k];
        atomicAdd(&out[o * TRAJ + tid], v);
    }
}

extern "C" void kernel_launch(void* const* d_in, const int* in_sizes, int n_in,
                              void* d_out, int out_size)
{
    const float* Df     = (const float*)d_in[0];
    const float* Dp     = (const float*)d_in[1];
    const float* goal   = (const float*)d_in[2];
    const float* L      = (const float*)d_in[3];
    const float* sdf    = (const float*)d_in[4];
    const float* minb   = (const float*)d_in[5];
    const int*   map_id = (const int*)d_in[6];
    float* out = (float*)d_out;

    const int outer = in_sizes[6];
    const int n_bt  = outer * TRAJ * NT;

    prelude_kernel<<<(n_bt + 255) / 256, 256>>>(Df, Dp, goal, L, minb, map_id,
                                                out, n_bt);
    dim3 grid(outer, NS / 2);
    gather_kernel<<<grid, 256>>>(sdf, map_id, out);
}